// round 3
// baseline (speedup 1.0000x reference)
#include <cuda_runtime.h>

#define HWPX (1024*1024)
#define NB 8
#define NA 8
#define NK 16
#define NSEG 17
#define EPSV 1e-4f

// per-batch constant block v2 (floats):
// [0,128)   : packed per-axis constants, axis a at [a*16]:
//             {A0,A0, A1,A1, A2,A2, dxi,dxi, m2,m2, pv0,pv0, pv1,pv1, pv2,pv2}
// [128,400) : tab[a][k] as float2 (slope, intercept), 8*17*2 = 272 floats
#define CB_PC   0
#define CB_TAB  128
#define CB_SIZE (128 + NA*NSEG*2)   // 400 floats

__device__ float g_consts[NB * CB_SIZE];

typedef unsigned long long ull;

__device__ __forceinline__ ull pk2(float lo, float hi) {
    ull r; asm("mov.b64 %0, {%1, %2};" : "=l"(r) : "f"(lo), "f"(hi)); return r;
}
__device__ __forceinline__ void upk2(ull v, float& lo, float& hi) {
    asm("mov.b64 {%0, %1}, %2;" : "=f"(lo), "=f"(hi) : "l"(v));
}
__device__ __forceinline__ ull fma2(ull a, ull b, ull c) {
    ull r; asm("fma.rn.f32x2 %0, %1, %2, %3;" : "=l"(r) : "l"(a), "l"(b), "l"(c)); return r;
}
__device__ __forceinline__ ull mul2(ull a, ull b) {
    ull r; asm("mul.rn.f32x2 %0, %1, %2;" : "=l"(r) : "l"(a), "l"(b)); return r;
}

__global__ void precompute_kernel(const float* __restrict__ ys,
                                  const float* __restrict__ A) {
    int b = blockIdx.x;
    int t = threadIdx.x;
    const float* Ab = A + b * 3 * NA;
    float* cb = g_consts + b * CB_SIZE;

    if (t < NA) {
        int a = t;
        float Am[3][NA];
        #pragma unroll
        for (int c = 0; c < 3; c++)
            #pragma unroll
            for (int j = 0; j < NA; j++)
                Am[c][j] = Ab[c * NA + j];

        // M = A * A^T  (3x3)
        float M[3][3];
        #pragma unroll
        for (int i = 0; i < 3; i++)
            #pragma unroll
            for (int j = 0; j < 3; j++) {
                float s = 0.f;
                #pragma unroll
                for (int k = 0; k < NA; k++) s += Am[i][k] * Am[j][k];
                M[i][j] = s;
            }

        // analytic 3x3 inverse
        float c00 = M[1][1]*M[2][2] - M[1][2]*M[2][1];
        float c01 = M[1][2]*M[2][0] - M[1][0]*M[2][2];
        float c02 = M[1][0]*M[2][1] - M[1][1]*M[2][0];
        float det = M[0][0]*c00 + M[0][1]*c01 + M[0][2]*c02;
        float id  = 1.0f / det;
        float inv[3][3];
        inv[0][0] = c00 * id;
        inv[1][0] = c01 * id;
        inv[2][0] = c02 * id;
        inv[0][1] = (M[0][2]*M[2][1] - M[0][1]*M[2][2]) * id;
        inv[1][1] = (M[0][0]*M[2][2] - M[0][2]*M[2][0]) * id;
        inv[2][1] = (M[0][1]*M[2][0] - M[0][0]*M[2][1]) * id;
        inv[0][2] = (M[0][1]*M[1][2] - M[0][2]*M[1][1]) * id;
        inv[1][2] = (M[0][2]*M[1][0] - M[0][0]*M[1][2]) * id;
        inv[2][2] = (M[0][0]*M[1][1] - M[0][1]*M[1][0]) * id;

        // pinv[a][c] = sum_k A[k][a] * inv[k][c]
        float pv[3];
        #pragma unroll
        for (int c = 0; c < 3; c++) {
            float s = 0.f;
            #pragma unroll
            for (int k = 0; k < 3; k++) s += Am[k][a] * inv[k][c];
            pv[c] = s;
        }

        float mn = 0.f, mx = 0.f;
        #pragma unroll
        for (int c = 0; c < 3; c++) {
            float v = Am[c][a];
            mn += fminf(v, 0.f);
            mx += fmaxf(v, 0.f);
        }
        float dx  = (mx + EPSV - mn) / 17.0f;
        float dxi = 1.0f / dx;
        float m2  = -mn * dxi;

        // packed (duplicated) per-axis constants
        float* pc = cb + CB_PC + a * 16;
        pc[0] = Am[0][a]; pc[1]  = Am[0][a];
        pc[2] = Am[1][a]; pc[3]  = Am[1][a];
        pc[4] = Am[2][a]; pc[5]  = Am[2][a];
        pc[6] = dxi;      pc[7]  = dxi;
        pc[8] = m2;       pc[9]  = m2;
        pc[10] = pv[0];   pc[11] = pv[0];
        pc[12] = pv[1];   pc[13] = pv[1];
        pc[14] = pv[2];   pc[15] = pv[2];

        // ys_full = [mins, ys[0..15], maxs]
        float ysf[18];
        ysf[0]  = mn;
        ysf[17] = mx;
        #pragma unroll
        for (int k = 0; k < NK; k++)
            ysf[k + 1] = ys[(b * NA + a) * NK + k];

        // per-segment (slope, intercept): est = (ys_hi - xs_hi*sl) + f*sl
        #pragma unroll
        for (int k = 0; k < NSEG; k++) {
            float sl    = (ysf[k + 1] - ysf[k]) / dx;
            float xs_hi = mn + (float)(k + 1) * dx;
            float c0    = ysf[k + 1] - xs_hi * sl;
            cb[CB_TAB + (a * NSEG + k) * 2 + 0] = sl;
            cb[CB_TAB + (a * NSEG + k) * 2 + 1] = c0;
        }
    }
}

__global__ __launch_bounds__(256)
void spline_main_kernel(const float* __restrict__ raw, float* __restrict__ out) {
    __shared__ __align__(16) float sc[CB_SIZE];
    const int b = blockIdx.y;
    {
        const float* cb = g_consts + b * CB_SIZE;
        for (int i = threadIdx.x; i < CB_SIZE; i += 256) sc[i] = cb[i];
    }
    __syncthreads();

    const ull*    pc   = (const ull*)(sc + CB_PC);       // 8 packed consts per axis
    const float2* stab = (const float2*)(sc + CB_TAB);

    const size_t base = (size_t)b * 3 * HWPX;
    const int vidx = blockIdx.x * 256 + threadIdx.x;     // float4 index within plane

    float4 R  = ((const float4*)(raw + base          ))[vidx];
    float4 G  = ((const float4*)(raw + base +   HWPX ))[vidx];
    float4 Bv = ((const float4*)(raw + base + 2*HWPX ))[vidx];

    ull r01 = pk2(R.x,  R.y),  r23 = pk2(R.z,  R.w);
    ull g01 = pk2(G.x,  G.y),  g23 = pk2(G.z,  G.w);
    ull b01 = pk2(Bv.x, Bv.y), b23 = pk2(Bv.z, Bv.w);

    ull acc0_01 = 0ULL, acc1_01 = 0ULL, acc2_01 = 0ULL;
    ull acc0_23 = 0ULL, acc1_23 = 0ULL, acc2_23 = 0ULL;

    #pragma unroll
    for (int a = 0; a < NA; a++) {
        const ull A0  = pc[a * 8 + 0];
        const ull A1  = pc[a * 8 + 1];
        const ull A2  = pc[a * 8 + 2];
        const ull DXI = pc[a * 8 + 3];
        const ull M2  = pc[a * 8 + 4];
        const ull PV0 = pc[a * 8 + 5];
        const ull PV1 = pc[a * 8 + 6];
        const ull PV2 = pc[a * 8 + 7];
        const float2* atab = stab + a * NSEG;

        // pair 0 (pixels 0,1)
        {
            ull f  = fma2(r01, A0, fma2(g01, A1, mul2(b01, A2)));
            ull u  = fma2(f, DXI, M2);
            float ul, uh; upk2(u, ul, uh);
            int kl = (int)ul;      // u in [0,17) by construction; trunc handles -eps
            int kh = (int)uh;
            float2 tl = atab[kl];
            float2 th = atab[kh];
            ull slp = pk2(tl.x, th.x);
            ull c0p = pk2(tl.y, th.y);
            ull est = fma2(f, slp, c0p);
            acc0_01 = fma2(est, PV0, acc0_01);
            acc1_01 = fma2(est, PV1, acc1_01);
            acc2_01 = fma2(est, PV2, acc2_01);
        }
        // pair 1 (pixels 2,3)
        {
            ull f  = fma2(r23, A0, fma2(g23, A1, mul2(b23, A2)));
            ull u  = fma2(f, DXI, M2);
            float ul, uh; upk2(u, ul, uh);
            int kl = (int)ul;
            int kh = (int)uh;
            float2 tl = atab[kl];
            float2 th = atab[kh];
            ull slp = pk2(tl.x, th.x);
            ull c0p = pk2(tl.y, th.y);
            ull est = fma2(f, slp, c0p);
            acc0_23 = fma2(est, PV0, acc0_23);
            acc1_23 = fma2(est, PV1, acc1_23);
            acc2_23 = fma2(est, PV2, acc2_23);
        }
    }

    float o0, o1, o2, o3;
    upk2(acc0_01, o0, o1); upk2(acc0_23, o2, o3);
    ((float4*)(out + base          ))[vidx] = make_float4(o0, o1, o2, o3);
    upk2(acc1_01, o0, o1); upk2(acc1_23, o2, o3);
    ((float4*)(out + base +   HWPX ))[vidx] = make_float4(o0, o1, o2, o3);
    upk2(acc2_01, o0, o1); upk2(acc2_23, o2, o3);
    ((float4*)(out + base + 2*HWPX ))[vidx] = make_float4(o0, o1, o2, o3);
}

extern "C" void kernel_launch(void* const* d_in, const int* in_sizes, int n_in,
                              void* d_out, int out_size) {
    const float* raw = (const float*)d_in[0];
    const float* ys  = (const float*)d_in[1];
    const float* A   = (const float*)d_in[2];
    float* out = (float*)d_out;

    precompute_kernel<<<NB, 32>>>(ys, A);

    dim3 grid(HWPX / (256 * 4), NB);
    spline_main_kernel<<<grid, 256>>>(raw, out);
}

// round 4
// speedup vs baseline: 1.7203x; 1.7203x over previous
#include <cuda_runtime.h>

#define HWPX (1024*1024)
#define NB 8
#define NA 8
#define NK 16
#define NSEG 17
#define EPSV 1e-4f

// per-batch constant block v3 (floats):
// [0,32)    : per-axis scalars, axis a at [a*4]: {A0*dxi, A1*dxi, A2*dxi, m2}
// [32,56)   : pinv rows, [a][3]
// [56,328)  : tab[a][k] as float2 (dy, c02), 8*17*2 = 272 floats
#define CB_AP   0
#define CB_PV   32
#define CB_TAB  56
#define CB_SIZE (56 + NA*NSEG*2)   // 328 floats

__device__ float g_consts[NB * CB_SIZE];

__global__ void precompute_kernel(const float* __restrict__ ys,
                                  const float* __restrict__ A) {
    int b = blockIdx.x;
    int t = threadIdx.x;
    const float* Ab = A + b * 3 * NA;
    float* cb = g_consts + b * CB_SIZE;

    if (t < NA) {
        int a = t;
        float Am[3][NA];
        #pragma unroll
        for (int c = 0; c < 3; c++)
            #pragma unroll
            for (int j = 0; j < NA; j++)
                Am[c][j] = Ab[c * NA + j];

        // M = A * A^T  (3x3)
        float M[3][3];
        #pragma unroll
        for (int i = 0; i < 3; i++)
            #pragma unroll
            for (int j = 0; j < 3; j++) {
                float s = 0.f;
                #pragma unroll
                for (int k = 0; k < NA; k++) s += Am[i][k] * Am[j][k];
                M[i][j] = s;
            }

        // analytic 3x3 inverse
        float c00 = M[1][1]*M[2][2] - M[1][2]*M[2][1];
        float c01 = M[1][2]*M[2][0] - M[1][0]*M[2][2];
        float c02 = M[1][0]*M[2][1] - M[1][1]*M[2][0];
        float det = M[0][0]*c00 + M[0][1]*c01 + M[0][2]*c02;
        float id  = 1.0f / det;
        float inv[3][3];
        inv[0][0] = c00 * id;
        inv[1][0] = c01 * id;
        inv[2][0] = c02 * id;
        inv[0][1] = (M[0][2]*M[2][1] - M[0][1]*M[2][2]) * id;
        inv[1][1] = (M[0][0]*M[2][2] - M[0][2]*M[2][0]) * id;
        inv[2][1] = (M[0][1]*M[2][0] - M[0][0]*M[2][1]) * id;
        inv[0][2] = (M[0][1]*M[1][2] - M[0][2]*M[1][1]) * id;
        inv[1][2] = (M[0][2]*M[1][0] - M[0][0]*M[1][2]) * id;
        inv[2][2] = (M[0][0]*M[1][1] - M[0][1]*M[1][0]) * id;

        // pinv[a][c] = sum_k A[k][a] * inv[k][c]
        #pragma unroll
        for (int c = 0; c < 3; c++) {
            float s = 0.f;
            #pragma unroll
            for (int k = 0; k < 3; k++) s += Am[k][a] * inv[k][c];
            cb[CB_PV + a * 3 + c] = s;
        }

        float mn = 0.f, mx = 0.f;
        #pragma unroll
        for (int c = 0; c < 3; c++) {
            float v = Am[c][a];
            mn += fminf(v, 0.f);
            mx += fmaxf(v, 0.f);
        }
        float dx  = (mx + EPSV - mn) / 17.0f;
        float dxi = 1.0f / dx;

        // scaled projection coefficients: u = r*A0' + g*A1' + b*A2' + m2
        cb[CB_AP + a * 4 + 0] = Am[0][a] * dxi;
        cb[CB_AP + a * 4 + 1] = Am[1][a] * dxi;
        cb[CB_AP + a * 4 + 2] = Am[2][a] * dxi;
        cb[CB_AP + a * 4 + 3] = -mn * dxi;

        // ys_full = [mins, ys[0..15], maxs]
        float ysf[18];
        ysf[0]  = mn;
        ysf[17] = mx;
        #pragma unroll
        for (int k = 0; k < NK; k++)
            ysf[k + 1] = ys[(b * NA + a) * NK + k];

        // est = ys_hi + (u - (k+1))*dy = fma(u, dy, c02)
        // dy_k = ysf[k+1]-ysf[k];  c02_k = ysf[k+1] - (k+1)*dy_k
        #pragma unroll
        for (int k = 0; k < NSEG; k++) {
            float dy  = ysf[k + 1] - ysf[k];
            float c02v = ysf[k + 1] - (float)(k + 1) * dy;
            cb[CB_TAB + (a * NSEG + k) * 2 + 0] = dy;
            cb[CB_TAB + (a * NSEG + k) * 2 + 1] = c02v;
        }
    }
}

__global__ __launch_bounds__(256, 5)
void spline_main_kernel(const float* __restrict__ raw, float* __restrict__ out) {
    __shared__ __align__(16) float sc[CB_SIZE];
    const int b = blockIdx.y;
    {
        const float* cb = g_consts + b * CB_SIZE;
        for (int i = threadIdx.x; i < CB_SIZE; i += 256) sc[i] = cb[i];
    }
    __syncthreads();

    const float*  sap  = sc + CB_AP;
    const float*  spv  = sc + CB_PV;
    const float2* stab = (const float2*)(sc + CB_TAB);

    const size_t base = (size_t)b * 3 * HWPX;
    const int vidx = blockIdx.x * 256 + threadIdx.x;   // float4 index within plane

    float4 R  = ((const float4*)(raw + base          ))[vidx];
    float4 G  = ((const float4*)(raw + base +   HWPX ))[vidx];
    float4 Bv = ((const float4*)(raw + base + 2*HWPX ))[vidx];

    float rr[4] = {R.x,  R.y,  R.z,  R.w};
    float gg[4] = {G.x,  G.y,  G.z,  G.w};
    float bb[4] = {Bv.x, Bv.y, Bv.z, Bv.w};

    float a0[4], a1[4], a2[4];
    #pragma unroll
    for (int q = 0; q < 4; q++) { a0[q] = 0.f; a1[q] = 0.f; a2[q] = 0.f; }

    #pragma unroll
    for (int a = 0; a < NA; a++) {
        const float A0  = sap[a * 4 + 0];
        const float A1  = sap[a * 4 + 1];
        const float A2  = sap[a * 4 + 2];
        const float M2  = sap[a * 4 + 3];
        const float pv0 = spv[a * 3 + 0];
        const float pv1 = spv[a * 3 + 1];
        const float pv2 = spv[a * 3 + 2];
        const float2* atab = stab + a * NSEG;
        #pragma unroll
        for (int q = 0; q < 4; q++) {
            // u in [0,17) by construction (EPS margin >> roundoff); trunc handles -eps
            float u = fmaf(rr[q], A0, fmaf(gg[q], A1, fmaf(bb[q], A2, M2)));
            int   k = (int)u;
            float2 tc = atab[k];
            float est = fmaf(u, tc.x, tc.y);
            a0[q] = fmaf(est, pv0, a0[q]);
            a1[q] = fmaf(est, pv1, a1[q]);
            a2[q] = fmaf(est, pv2, a2[q]);
        }
    }

    ((float4*)(out + base          ))[vidx] = make_float4(a0[0], a0[1], a0[2], a0[3]);
    ((float4*)(out + base +   HWPX ))[vidx] = make_float4(a1[0], a1[1], a1[2], a1[3]);
    ((float4*)(out + base + 2*HWPX ))[vidx] = make_float4(a2[0], a2[1], a2[2], a2[3]);
}

extern "C" void kernel_launch(void* const* d_in, const int* in_sizes, int n_in,
                              void* d_out, int out_size) {
    const float* raw = (const float*)d_in[0];
    const float* ys  = (const float*)d_in[1];
    const float* A   = (const float*)d_in[2];
    float* out = (float*)d_out;

    precompute_kernel<<<NB, 32>>>(ys, A);

    dim3 grid(HWPX / (256 * 4), NB);
    spline_main_kernel<<<grid, 256>>>(raw, out);
}